// round 17
// baseline (speedup 1.0000x reference)
#include <cuda_runtime.h>

// Fixed shapes: x = (4,64,256,256) f32, stoken = 16
#define Bn 4
#define Cc 64
#define NH 16      // superpixel grid 16x16
#define NS 256     // nH*nW
#define PP 65536   // H*W
#define NCTA 1024  // grid size (NS * Bn)

typedef unsigned long long ull;

// Scratch (allocation-free: __device__ globals)
__device__ float g_cent[Bn * NS * Cc];
__device__ float g_num [Bn * NS * Cc];
__device__ float g_den [Bn * NS];
__device__ unsigned int g_barcnt;   // zero-initialized at module load
__device__ unsigned int g_bargen;

__device__ __forceinline__ void ffma2(ull& acc, ull a, ull b) {
    asm("fma.rn.f32x2 %0, %1, %2, %0;" : "+l"(acc) : "l"(a), "l"(b));
}
__device__ __forceinline__ ull pack2(float x, float y) {
    ull r; asm("mov.b64 %0, {%1, %2};" : "=l"(r) : "f"(x), "f"(y)); return r;
}
__device__ __forceinline__ float2 unpack2(ull v) {
    float2 r; asm("mov.b64 {%0, %1}, %2;" : "=f"(r.x), "=f"(r.y) : "l"(v)); return r;
}

// Self-resetting software grid barrier (all NCTA CTAs are co-resident:
// launch_bounds(128,8) caps regs at 64 -> capacity >= 1184 > 1024).
// Generation counter is monotonic across graph replays; count resets to 0.
__device__ __forceinline__ void grid_barrier() {
    __syncthreads();
    if (threadIdx.x == 0) {
        unsigned int gen = *(volatile unsigned int*)&g_bargen;
        __threadfence();
        if (atomicAdd(&g_barcnt, 1u) == NCTA - 1u) {
            g_barcnt = 0;
            __threadfence();
            atomicAdd(&g_bargen, 1u);
        } else {
            while (*(volatile unsigned int*)&g_bargen == gen) { }
        }
    }
    __syncthreads();
}

// ---------------------------------------------------------------------------
// Zero-fill a slice [lo,hi) of plane (b,s), skipping float4s inside the 3x3
// affinity region (written by phase C's scatter — byte-disjoint). Streaming
// evict-first stores: they drain while compute stalls, and keep x in L2.
// ---------------------------------------------------------------------------
__device__ __forceinline__ void fill_slice(float4* __restrict__ A, int b, int s,
                                           int lo, int hi, int tid) {
    int si = s >> 4, sj = s & 15;
    float4* plane = A + ((size_t)(b * NS + s) << 14);   // 16384 float4 per plane
    const float4 z = make_float4(0.f, 0.f, 0.f, 0.f);
    #pragma unroll 4
    for (int e4 = lo + tid; e4 < hi; e4 += 128) {
        int p = e4 << 2;
        int bi = p >> 12;
        int bj = (p >> 4) & 15;
        int di = si - bi + 1, dj = sj - bj + 1;
        if ((unsigned)di > 2u || (unsigned)dj > 2u)
            __stcs(&plane[e4], z);
    }
}

#define FILL_A_END 4096
#define FILL_B_END 10240

#define SOFTMAX9(a) do {                                                \
    float mx = -3.0e38f;                                                \
    _Pragma("unroll") for (int k = 0; k < 9; k++) mx = fmaxf(mx, a[k]); \
    float ss = 0.f;                                                     \
    _Pragma("unroll") for (int k = 0; k < 9; k++) { a[k] = __expf(a[k] - mx); ss += a[k]; } \
    float rs = 1.f / ss;                                                \
    _Pragma("unroll") for (int k = 0; k < 9; k++) a[k] *= rs;           \
} while (0)

// ---------------------------------------------------------------------------
// ONE persistent kernel, 3 phases separated by grid barriers.
// CTA = 128 threads = one (b, 16x16 block). x is read from DRAM exactly once
// (phase A); phases B and C re-read it from L2.
// ---------------------------------------------------------------------------
__global__ __launch_bounds__(128, 8) void gensp_fused_kernel(
        const float* __restrict__ x, float* __restrict__ A) {
    int b = blockIdx.y, sblk = blockIdx.x;
    int bi = sblk >> 4, bj = sblk & 15;
    int tid = threadIdx.x;

    __shared__ __align__(16) ull cent2_sm[9][64];   // (-2c, -2c) per channel
    __shared__ __align__(16) ull aff_sm[9][128];    // pair-packed (phase B)
    __shared__ float c2_sm[9];
    __shared__ float c2part[9][8];
    __shared__ float den_sm[9];
    __shared__ int   cand_s[9];
    __shared__ int   cand_v[9];
    __shared__ float denpart[4][9];

    if (tid < 9) {
        int ci = bi + tid / 3 - 1, cj = bj + tid % 3 - 1;
        int v = (ci >= 0 && ci < NH && cj >= 0 && cj < NH);
        cand_v[tid] = v;
        cand_s[tid] = v ? ci * NH + cj : 0;
    }

    int base = ((bi * 16) << 8) + bj * 16;          // block's pixel base

    // ================= PHASE A: block mean (the only cold x read) ==========
    fill_slice((float4*)A, b, sblk, 0, FILL_A_END, tid);
    {
        int c = tid >> 1, g = tid & 1;
        const float* fc = x + (((size_t)(b * Cc + c)) << 16);
        float s = 0.f;
        #pragma unroll 4
        for (int t = 0; t < 32; t++) {
            int j = t * 2 + g;                       // quad index 0..63
            int r = j >> 2, c4 = j & 3;
            float4 fq = *(const float4*)(fc + base + (r << 8) + c4 * 4);
            s += (fq.x + fq.y) + (fq.z + fq.w);
        }
        s += __shfl_xor_sync(0xffffffffu, s, 1);     // partner merge
        if (g == 0) {
            int idx = (b * NS + sblk) * Cc + c;
            g_cent[idx] = s * (1.f / 256.f);
            g_num[idx]  = 0.f;
        }
        if (tid == 0) g_den[b * NS + sblk] = 0.f;
    }
    grid_barrier();

    // ================= PHASE B: affinity + fused num/den ===================
    fill_slice((float4*)A, b, sblk, FILL_A_END, FILL_B_END, tid);
    for (int i = tid; i < 9 * 64; i += 128) {
        int k = i >> 6, c = i & 63;
        float cv = g_cent[(b * NS + cand_s[k]) * Cc + c];
        float t2 = -2.f * cv;
        cent2_sm[k][c] = pack2(t2, t2);
    }
    __syncthreads();
    if (tid < 72) {
        int k = tid >> 3, c0 = (tid & 7) << 3;
        float s2 = 0.f;
        #pragma unroll
        for (int c = 0; c < 8; c++) {
            float2 h = unpack2(cent2_sm[k][c0 + c]);
            s2 = fmaf(h.x, h.x, s2);
        }
        c2part[k][tid & 7] = s2;
    }
    __syncthreads();
    if (tid < 9) {
        float s = 0.f;
        #pragma unroll
        for (int w = 0; w < 8; w++) s += c2part[tid][w];
        c2_sm[tid] = 0.25f * s;
    }
    __syncthreads();

    int row = tid >> 3, cp = tid & 7;
    int p0 = ((bi * 16 + row) << 8) + bj * 16 + (cp << 1);   // pixel pair base
    const float* fb = x + (((size_t)b * Cc) << 16) + p0;

    {
        ull dacc[9];
        #pragma unroll
        for (int k = 0; k < 9; k++) dacc[k] = 0ull;
        #pragma unroll
        for (int cc = 0; cc < 64; cc += 8) {
            ull f[8];
            #pragma unroll
            for (int j = 0; j < 8; j++)
                f[j] = *(const ull*)(fb + ((size_t)(cc + j) << 16));
            #pragma unroll
            for (int j = 0; j < 8; j += 2) {
                #pragma unroll
                for (int k = 0; k < 9; k++) {
                    ulonglong2 cv = *(const ulonglong2*)&cent2_sm[k][cc + j];
                    ffma2(dacc[k], f[j],     cv.x);
                    ffma2(dacc[k], f[j + 1], cv.y);
                }
            }
        }
        float a0[9], a1[9];
        #pragma unroll
        for (int k = 0; k < 9; k++) {
            float2 dh = unpack2(dacc[k]);
            float cb = c2_sm[k];
            bool v = cand_v[k] != 0;
            a0[k] = v ? -(cb + dh.x) : -1e30f;
            a1[k] = v ? -(cb + dh.y) : -1e30f;
        }
        SOFTMAX9(a0); SOFTMAX9(a1);
        #pragma unroll
        for (int k = 0; k < 9; k++)
            if (!cand_v[k]) { a0[k] = 0.f; a1[k] = 0.f; }

        float ds[9];
        #pragma unroll
        for (int k = 0; k < 9; k++) {
            aff_sm[k][tid] = pack2(a0[k], a1[k]);
            ds[k] = a0[k] + a1[k];
        }
        #pragma unroll
        for (int k = 0; k < 9; k++) {
            float v = ds[k];
            v += __shfl_xor_sync(0xffffffffu, v, 16);
            v += __shfl_xor_sync(0xffffffffu, v, 8);
            v += __shfl_xor_sync(0xffffffffu, v, 4);
            v += __shfl_xor_sync(0xffffffffu, v, 2);
            v += __shfl_xor_sync(0xffffffffu, v, 1);
            if ((tid & 31) == 0) denpart[tid >> 5][k] = v;
        }
        __syncthreads();

        // num[k][c]: thread = (channel, half); LDG.128 quads (L1/L2 hot)
        int c = tid >> 1, g = tid & 1;
        const float* fc = x + (((size_t)(b * Cc + c)) << 16);
        ull acc[9];
        #pragma unroll
        for (int k = 0; k < 9; k++) acc[k] = 0ull;
        #pragma unroll 4
        for (int t = 0; t < 32; t++) {
            int j = t * 2 + g;                         // quad index 0..63
            int r = j >> 2, c4 = j & 3;
            float4 fq = *(const float4*)(fc + base + (r << 8) + c4 * 4);
            ull u01 = pack2(fq.x, fq.y), u23 = pack2(fq.z, fq.w);
            #pragma unroll
            for (int k = 0; k < 9; k++) {
                ulonglong2 aq = *(const ulonglong2*)&aff_sm[k][j * 2];
                ffma2(acc[k], u01, aq.x);
                ffma2(acc[k], u23, aq.y);
            }
        }
        #pragma unroll
        for (int k = 0; k < 9; k++) {
            float2 h = unpack2(acc[k]);
            float v = h.x + h.y;
            v += __shfl_xor_sync(0xffffffffu, v, 1);   // partner merge
            if (g == 0 && cand_v[k])
                atomicAdd(&g_num[(b * NS + cand_s[k]) * Cc + c], v);
        }
        if (tid < 9 && cand_v[tid]) {
            float v = (denpart[0][tid] + denpart[1][tid])
                    + (denpart[2][tid] + denpart[3][tid]);
            atomicAdd(&g_den[b * NS + cand_s[tid]], v);
        }
    }
    grid_barrier();

    // ================= PHASE C: finalize cent + affinity + scatter =========
    fill_slice((float4*)A, b, sblk, FILL_B_END, 16384, tid);
    if (tid < 9)
        den_sm[tid] = g_den[b * NS + cand_s[tid]] + 1e-16f;
    __syncthreads();
    for (int i = tid; i < 9 * 64; i += 128) {
        int k = i >> 6, c = i & 63;
        float cv = g_num[(b * NS + cand_s[k]) * Cc + c] / den_sm[k];
        float t2 = -2.f * cv;
        cent2_sm[k][c] = pack2(t2, t2);
    }
    __syncthreads();
    if (tid < 72) {
        int k = tid >> 3, c0 = (tid & 7) << 3;
        float s2 = 0.f;
        #pragma unroll
        for (int c = 0; c < 8; c++) {
            float2 h = unpack2(cent2_sm[k][c0 + c]);
            s2 = fmaf(h.x, h.x, s2);
        }
        c2part[k][tid & 7] = s2;
    }
    __syncthreads();
    if (tid < 9) {
        float s = 0.f;
        #pragma unroll
        for (int w = 0; w < 8; w++) s += c2part[tid][w];
        c2_sm[tid] = 0.25f * s;
    }
    __syncthreads();

    {
        ull dacc[9];
        #pragma unroll
        for (int k = 0; k < 9; k++) dacc[k] = 0ull;
        #pragma unroll
        for (int cc = 0; cc < 64; cc += 8) {
            ull f[8];
            #pragma unroll
            for (int j = 0; j < 8; j++)
                f[j] = *(const ull*)(fb + ((size_t)(cc + j) << 16));
            #pragma unroll
            for (int j = 0; j < 8; j += 2) {
                #pragma unroll
                for (int k = 0; k < 9; k++) {
                    ulonglong2 cv = *(const ulonglong2*)&cent2_sm[k][cc + j];
                    ffma2(dacc[k], f[j],     cv.x);
                    ffma2(dacc[k], f[j + 1], cv.y);
                }
            }
        }
        float a0[9], a1[9];
        #pragma unroll
        for (int k = 0; k < 9; k++) {
            float2 dh = unpack2(dacc[k]);
            float cb = c2_sm[k];
            bool v = cand_v[k] != 0;
            a0[k] = v ? -(cb + dh.x) : -1e30f;
            a1[k] = v ? -(cb + dh.y) : -1e30f;
        }
        SOFTMAX9(a0); SOFTMAX9(a1);
        #pragma unroll
        for (int k = 0; k < 9; k++) {
            if (cand_v[k]) {
                size_t off = (((size_t)(b * NS + cand_s[k])) << 16) + p0;
                __stcs((float2*)(A + off), make_float2(a0[k], a1[k]));
            }
        }
    }
}

extern "C" void kernel_launch(void* const* d_in, const int* in_sizes, int n_in,
                              void* d_out, int out_size) {
    const float* x = (const float*)d_in[0];
    float* A = (float*)d_out;
    dim3 grid(NS, Bn);
    gensp_fused_kernel<<<grid, 128>>>(x, A);
}